// round 15
// baseline (speedup 1.0000x reference)
#include <cuda_runtime.h>
#include <math.h>

#define BB 8
#define NN1 64
#define NN2 512
#define DD 128
#define NL 3
#define NT 7
#define R1T (BB*NN1)            // 512
#define R2T (BB*NN2)            // 4096
#define RTOT (R1T+R2T)          // 4608
#define CAP 96
#define NBLKP 256

// ---------------- scratch ----------------
__device__ __align__(16) float g_x  [RTOT*DD];
__device__ __align__(16) float g_xT [DD*RTOT];
__device__ __align__(16) float g_hc [RTOT*256];
__device__ __align__(16) float g_e1 [BB*NN1*NN1];
__device__ __align__(16) float g_e2 [BB*NN2*NN2];
__device__ __align__(16) float g_wc [NL*DD*256];
__device__ __align__(16) float g_bc [NL*256];
__device__ __align__(16) float g_u1 [14*R1T*DD];
__device__ __align__(16) float g_u2 [14*R2T*DD];
__device__ __align__(16) unsigned char g_maskb[BB*NN1*NN2];
__device__ float g_dm[BB*NN1*NN2];
__device__ float g_partial[BB*NBLKP*NT];
__device__ int   g_rl[RTOT*CAP];
__device__ int   g_rcnt[RTOT];
__device__ int   g_cl[RTOT*CAP];
__device__ int   g_ccnt[RTOT];

__constant__ float BCON[7] = {1.159f,0.448f,0.927f,0.902f,0.349f,0.789f,0.198f};

// ---------------- f32x2 / cp.async helpers ----------------
__device__ __forceinline__ unsigned long long dup_f32(float x)
{
    unsigned long long d;
    asm("mov.b64 %0, {%1, %1};" : "=l"(d) : "f"(x));
    return d;
}
__device__ __forceinline__ void ffma2(unsigned long long& acc, unsigned long long a, unsigned long long b)
{
    asm("fma.rn.f32x2 %0, %1, %2, %0;" : "+l"(acc) : "l"(a), "l"(b));
}
__device__ __forceinline__ float2 unpk(unsigned long long v)
{
    float lo, hi;
    asm("mov.b64 {%0, %1}, %2;" : "=f"(lo), "=f"(hi) : "l"(v));
    return make_float2(lo, hi);
}
__device__ __forceinline__ void cpa16(void* smem, const void* g)
{
    unsigned a = (unsigned)__cvta_generic_to_shared(smem);
    asm volatile("cp.async.cg.shared.global [%0], [%1], 16;" :: "r"(a), "l"(g));
}
#define CP_COMMIT() asm volatile("cp.async.commit_group;" ::: "memory")
#define CP_WAIT(n)  asm volatile("cp.async.wait_group %0;" :: "n"(n) : "memory")

// ---------------- 32x128 tile GEMM (scalar, K guarded) ----------------
__device__ __forceinline__ void gemm32_tile(
    const float* __restrict__ A, int lda, int K,
    const float* __restrict__ B, int ldb,
    float* __restrict__ C, int ldc,
    float* As /*32*36*/, float* Bs /*32*128*/)
{
    int t = threadIdx.x, rq = t >> 5, cq = t & 31;
    float acc[4][4];
#pragma unroll
    for (int i = 0; i < 4; i++)
#pragma unroll
        for (int j = 0; j < 4; j++) acc[i][j] = 0.f;
    for (int k0 = 0; k0 < K; k0 += 32) {
#pragma unroll
        for (int s = 0; s < 4; s++) {
            int i = t + 256 * s, r = i >> 5, kk = i & 31, gk = k0 + kk;
            As[kk * 36 + r] = (gk < K) ? A[r * lda + gk] : 0.f;
        }
#pragma unroll
        for (int s = 0; s < 16; s++) {
            int i = t + 256 * s, kk = i >> 7, c = i & 127, gk = k0 + kk;
            Bs[kk * 128 + c] = (gk < K) ? B[gk * ldb + c] : 0.f;
        }
        __syncthreads();
#pragma unroll
        for (int kk = 0; kk < 32; kk++) {
            float4 av = *(const float4*)&As[kk * 36 + rq * 4];
            float4 bv = *(const float4*)&Bs[kk * 128 + cq * 4];
            float ar[4] = {av.x, av.y, av.z, av.w};
            float br[4] = {bv.x, bv.y, bv.z, bv.w};
#pragma unroll
            for (int i = 0; i < 4; i++)
#pragma unroll
                for (int j = 0; j < 4; j++) acc[i][j] += ar[i] * br[j];
        }
        __syncthreads();
    }
#pragma unroll
    for (int i = 0; i < 4; i++) {
        float4 o;
        o.x = acc[i][0]; o.y = acc[i][1]; o.z = acc[i][2]; o.w = acc[i][3];
        *(float4*)&C[(rq * 4 + i) * ldc + cq * 4] = o;
    }
}

// ---------------- 64x128 tile GEMM, K=128, FFMA2 inner (sync staging) ----------------
__device__ __forceinline__ void gemm64_tile(
    const float* __restrict__ A, int lda,
    const float* __restrict__ B, int ldb,
    const float* __restrict__ bias,
    float* __restrict__ C, int ldc,
    float* As /*32*68*/, float* Bs /*32*128*/)
{
    int t = threadIdx.x, w = t >> 5, lane = t & 31;
    unsigned long long acc2[4][4];
#pragma unroll
    for (int p = 0; p < 4; p++)
#pragma unroll
        for (int j = 0; j < 4; j++) acc2[p][j] = 0ull;
    for (int k0 = 0; k0 < 128; k0 += 32) {
#pragma unroll
        for (int s = 0; s < 8; s++) {
            int i = t + 256 * s, r = i >> 5, kk = i & 31;
            As[kk * 68 + r] = A[r * lda + k0 + kk];
        }
#pragma unroll
        for (int s = 0; s < 16; s++) {
            int i = t + 256 * s, kk = i >> 7, c = i & 127;
            Bs[kk * 128 + c] = B[(k0 + kk) * ldb + c];
        }
        __syncthreads();
#pragma unroll
        for (int kk = 0; kk < 32; kk++) {
            const ulonglong2* ap = (const ulonglong2*)&As[kk * 68 + w * 8];
            ulonglong2 a0 = ap[0], a1 = ap[1];
            unsigned long long ar[4] = {a0.x, a0.y, a1.x, a1.y};
            float4 bv = *(const float4*)&Bs[kk * 128 + lane * 4];
            unsigned long long br[4] = {dup_f32(bv.x), dup_f32(bv.y), dup_f32(bv.z), dup_f32(bv.w)};
#pragma unroll
            for (int p = 0; p < 4; p++)
#pragma unroll
                for (int j = 0; j < 4; j++) ffma2(acc2[p][j], ar[p], br[j]);
        }
        __syncthreads();
    }
    float4 bvv = make_float4(0.f, 0.f, 0.f, 0.f);
    if (bias) bvv = *(const float4*)&bias[lane * 4];
#pragma unroll
    for (int p = 0; p < 4; p++) {
        float2 v0 = unpk(acc2[p][0]), v1 = unpk(acc2[p][1]);
        float2 v2 = unpk(acc2[p][2]), v3 = unpk(acc2[p][3]);
        float4 olo, ohi;
        olo.x = v0.x + bvv.x; olo.y = v1.x + bvv.y; olo.z = v2.x + bvv.z; olo.w = v3.x + bvv.w;
        ohi.x = v0.y + bvv.x; ohi.y = v1.y + bvv.y; ohi.z = v2.y + bvv.z; ohi.w = v3.y + bvv.w;
        *(float4*)&C[(w * 8 + 2 * p) * ldc + lane * 4] = olo;
        *(float4*)&C[(w * 8 + 2 * p + 1) * ldc + lane * 4] = ohi;
    }
}

// ---------------- prep: weights || col-lists || row-lists || mask+dm || embed ----------------
#define PB_A 192
#define PB_B (PB_A + 18)
#define PB_C (PB_B + 576)
#define PB_D (PB_C + 1024)
#define PB_E (PB_D + 144)

__global__ void prep(const float* __restrict__ h1, const float* __restrict__ h2,
                     const float* __restrict__ adj1, const float* __restrict__ adj2,
                     const float* __restrict__ A_int, const float* __restrict__ dmv,
                     const float* __restrict__ W_embed,
                     const float* __restrict__ gW, const float* __restrict__ gA,
                     const float* __restrict__ gWb)
{
    __shared__ __align__(16) float shA[32 * 36];
    __shared__ __align__(16) float shB[32 * 128];
    int bx = blockIdx.x, t = threadIdx.x;

    if (bx < PB_A) {
        int idx = bx * 256 + t;
        int c = idx & 127, d = (idx >> 7) & 127, l = idx >> 14;
        const float* W = gW + l * DD * DD;
        const float* Am = gA + l * DD * DD;
        g_wc[(l * DD + d) * 256 + c] = W[d * DD + c];
        float s = 0.f;
#pragma unroll 8
        for (int dd = 0; dd < DD; dd++) s += W[d * DD + dd] * Am[dd * DD + c];
        g_wc[(l * DD + d) * 256 + 128 + c] = s;
        if (d == 0) {
            g_bc[l * 256 + c] = gWb[l * DD + c];
            float sb = 0.f;
#pragma unroll 8
            for (int dd = 0; dd < DD; dd++) sb += gWb[l * DD + dd] * Am[dd * DD + c];
            g_bc[l * 256 + 128 + c] = sb;
        }
    } else if (bx < PB_B) {
        int cidx = (bx - PB_A) * 256 + t;
        const float* aj; int N, c;
        if (cidx < R1T) { int b = cidx >> 6; c = cidx & 63; N = NN1; aj = adj1 + b * NN1 * NN1; }
        else { int rr = cidx - R1T; int b = rr >> 9; c = rr & 511; N = NN2; aj = adj2 + b * NN2 * NN2; }
        int cnt = 0;
        for (int r = 0; r < N; r++) {
            if (aj[r * N + c] != 0.f) { if (cnt < CAP) g_cl[cidx * CAP + cnt] = r; cnt++; }
        }
        g_ccnt[cidx] = (cnt > CAP) ? CAP : cnt;
    } else if (bx < PB_C) {
        int row = (bx - PB_B) * 8 + (t >> 5);
        int lane = t & 31;
        const float* aj; int N;
        if (row < R1T) { int b = row >> 6, r = row & 63; N = NN1; aj = adj1 + (b * NN1 + r) * NN1; }
        else { int rr = row - R1T; int b = rr >> 9, r = rr & 511; N = NN2; aj = adj2 + (b * NN2 + r) * NN2; }
        int cnt = 0;
        for (int base = 0; base < N; base += 32) {
            int c = base + lane;
            bool v = (aj[c] != 0.f);
            unsigned m = __ballot_sync(0xffffffffu, v);
            if (v) {
                int pos = cnt + __popc(m & ((1u << lane) - 1u));
                if (pos < CAP) g_rl[row * CAP + pos] = c;
            }
            cnt += __popc(m);
        }
        if (cnt > CAP) cnt = CAP;
        if (lane == 0) g_rcnt[row] = cnt;
    } else if (bx < PB_D) {
        int v = (bx - PB_C) * 256 + t;
        int k = v & 511, j = (v >> 9) & 63, b = v >> 15;
        unsigned m = 0;
#pragma unroll
        for (int i = 0; i < 7; i++)
            if (A_int[((b * 7 + i) * NN1 + j) * NN2 + k] != 0.f) m |= 1u << i;
        int po = b * 32768 + k * 64 + j;
        g_maskb[po] = (unsigned char)m;
        int pidx = (b * NN1 + j) * NN2 + k;
        float d0 = dmv[pidx * 3 + 0], d1 = dmv[pidx * 3 + 1], d2 = dmv[pidx * 3 + 2];
        float dm = sqrtf(d0 * d0 + d1 * d1 + d2 * d2 + 1e-10f);
        if (dm < 0.5f) dm = 1e10f;
        g_dm[po] = dm;
    } else {
        int tile = bx - PB_D;
        int row0 = tile * 32;
        const float* Ap = (row0 < R1T) ? (h1 + row0 * 56) : (h2 + (row0 - R1T) * 56);
        gemm32_tile(Ap, 56, 56, W_embed, 128, g_x + row0 * 128, 128, shA, shB);
    }
}

// ---------------- layer GEMM: hc = x @ Wc + bc ----------------
__global__ void gemm_hc(const float* __restrict__ wc_l, const float* __restrict__ bc_l)
{
    __shared__ __align__(16) float shA[32 * 68];
    __shared__ __align__(16) float shB[32 * 128];
    cudaGridDependencySynchronize();
    int rowtile = blockIdx.x >> 1, colb = blockIdx.x & 1;
    gemm64_tile(g_x + rowtile * 64 * 128, 128,
                wc_l + colb * 128, 256,
                bc_l + colb * 128,
                g_hc + rowtile * 64 * 256 + colb * 128, 256, shA, shB);
}

// ---------------- column pass: e -> normalized att (4 warps/column, reg-preloaded list) ----------------
__global__ void stats_e()
{
    __shared__ float smx[2][4];
    __shared__ float ssum[2][4];
    cudaGridDependencySynchronize();
    int w = threadIdx.x >> 5, lane = threadIdx.x & 31;
    int cq = w >> 2, qt = w & 3;
    int cidx = blockIdx.x * 2 + cq;
    int N, c, gbase; float* E;
    if (cidx < R1T) { int b = cidx >> 6; c = cidx & 63; N = NN1; gbase = b * NN1; E = g_e1 + b * NN1 * NN1; }
    else { int rr = cidx - R1T; int b = rr >> 9; c = rr & 511; N = NN2; gbase = R1T + b * NN2; E = g_e2 + b * NN2 * NN2; }

    float4 hcv  = *(const float4*)&g_hc[(gbase + c) * 256 + lane * 4];
    float4 hacv = *(const float4*)&g_hc[(gbase + c) * 256 + 128 + lane * 4];
    int cnt = g_ccnt[cidx];
    const int* cl = g_cl + cidx * CAP;
    int qlen = (cnt + 3) >> 2;
    int s0 = qt * qlen;
    int s1 = s0 + qlen; if (s1 > cnt) s1 = cnt;
    int len = s1 - s0; if (len < 0) len = 0;      // <= 24

    // register-preload this quarter's neighbor indices (one lane-parallel LDG)
    int myc = (lane < len) ? cl[s0 + lane] : 0;

    float ebuf = 0.f;
    float mx = -1e30f;
    int idx = 0;
    for (; idx + 4 <= len; idx += 4) {
        float e[4];
#pragma unroll
        for (int u = 0; u < 4; u++) {
            int r = __shfl_sync(0xffffffffu, myc, idx + u);
            const float* pr = &g_hc[(gbase + r) * 256 + lane * 4];
            float4 h = *(const float4*)pr;
            float4 ha = *(const float4*)(pr + 128);
            e[u] = hacv.x * h.x + hacv.y * h.y + hacv.z * h.z + hacv.w * h.w
                 + hcv.x * ha.x + hcv.y * ha.y + hcv.z * ha.z + hcv.w * ha.w;
        }
#pragma unroll
        for (int o = 16; o; o >>= 1) {
#pragma unroll
            for (int u = 0; u < 4; u++)
                e[u] += __shfl_xor_sync(0xffffffffu, e[u], o);
        }
#pragma unroll
        for (int u = 0; u < 4; u++) {
            if (lane == (idx + u)) ebuf = e[u];
            mx = fmaxf(mx, e[u]);
        }
    }
    for (; idx < len; idx++) {
        int r = __shfl_sync(0xffffffffu, myc, idx);
        const float* pr = &g_hc[(gbase + r) * 256 + lane * 4];
        float4 hr = *(const float4*)pr, har = *(const float4*)(pr + 128);
        float p = hacv.x * hr.x + hacv.y * hr.y + hacv.z * hr.z + hacv.w * hr.w
                + hcv.x * har.x + hcv.y * har.y + hcv.z * har.z + hcv.w * har.w;
#pragma unroll
        for (int o = 16; o; o >>= 1) p += __shfl_xor_sync(0xffffffffu, p, o);
        if (lane == idx) ebuf = p;
        mx = fmaxf(mx, p);
    }
    if (lane == 0) smx[cq][qt] = mx;
    __syncthreads();
    float gmx = fmaxf(fmaxf(smx[cq][0], smx[cq][1]), fmaxf(smx[cq][2], smx[cq][3]));

    float vb = 0.f;
    float s = 0.f;
    if (lane < len) { vb = expf(ebuf - gmx); s = vb; }
#pragma unroll
    for (int o = 16; o; o >>= 1) s += __shfl_xor_sync(0xffffffffu, s, o);
    if (lane == 0) ssum[cq][qt] = s;
    __syncthreads();
    float zi = 1.f / ((ssum[cq][0] + ssum[cq][1]) + (ssum[cq][2] + ssum[cq][3]));
    if (lane < len) E[myc * N + c] = vb * zi;
}

// ---------------- row pass: hp = relu(att@h); gate (4 warps/row, reg-preloaded list) ----------------
__global__ void att_gate(const float* __restrict__ Wg, const float* __restrict__ bg)
{
    __shared__ __align__(16) float shp[2][3][128];
    cudaGridDependencySynchronize();
    int w = threadIdx.x >> 5, lane = threadIdx.x & 31;
    int rq = w >> 2, qt = w & 3;
    int row = blockIdx.x * 2 + rq;
    int N, r, gbase; const float* E;
    if (row < R1T) { int b = row >> 6; r = row & 63; N = NN1; gbase = b * NN1; E = g_e1 + b * NN1 * NN1; }
    else { int rr = row - R1T; int b = rr >> 9; r = rr & 511; N = NN2; gbase = R1T + b * NN2; E = g_e2 + b * NN2 * NN2; }

    float4 acc0 = make_float4(0.f, 0.f, 0.f, 0.f);
    float4 acc1 = make_float4(0.f, 0.f, 0.f, 0.f);
    int cnt = g_rcnt[row];
    const int* rl = g_rl + row * CAP;
    const float* Er = E + r * N;
    int qlen = (cnt + 3) >> 2;
    int s0 = qt * qlen;
    int s1 = s0 + qlen; if (s1 > cnt) s1 = cnt;
    int len = s1 - s0; if (len < 0) len = 0;      // <= 24

    // register-preload this quarter's neighbor indices
    int myc = (lane < len) ? rl[s0 + lane] : 0;

    int idx = 0;
    for (; idx + 4 <= len; idx += 4) {
        int c0 = __shfl_sync(0xffffffffu, myc, idx);
        int c1 = __shfl_sync(0xffffffffu, myc, idx + 1);
        int c2 = __shfl_sync(0xffffffffu, myc, idx + 2);
        int c3 = __shfl_sync(0xffffffffu, myc, idx + 3);
        float w0 = Er[c0], w1 = Er[c1], w2 = Er[c2], w3 = Er[c3];
        float4 h0 = *(const float4*)&g_hc[(gbase + c0) * 256 + lane * 4];
        float4 h1 = *(const float4*)&g_hc[(gbase + c1) * 256 + lane * 4];
        float4 h2 = *(const float4*)&g_hc[(gbase + c2) * 256 + lane * 4];
        float4 h3 = *(const float4*)&g_hc[(gbase + c3) * 256 + lane * 4];
        acc0.x += w0 * h0.x; acc0.y += w0 * h0.y; acc0.z += w0 * h0.z; acc0.w += w0 * h0.w;
        acc1.x += w1 * h1.x; acc1.y += w1 * h1.y; acc1.z += w1 * h1.z; acc1.w += w1 * h1.w;
        acc0.x += w2 * h2.x; acc0.y += w2 * h2.y; acc0.z += w2 * h2.z; acc0.w += w2 * h2.w;
        acc1.x += w3 * h3.x; acc1.y += w3 * h3.y; acc1.z += w3 * h3.z; acc1.w += w3 * h3.w;
    }
    for (; idx < len; idx++) {
        int cc = __shfl_sync(0xffffffffu, myc, idx);
        float wv = Er[cc];
        float4 hv = *(const float4*)&g_hc[(gbase + cc) * 256 + lane * 4];
        acc0.x += wv * hv.x; acc0.y += wv * hv.y; acc0.z += wv * hv.z; acc0.w += wv * hv.w;
    }
    float4 acc;
    acc.x = acc0.x + acc1.x;
    acc.y = acc0.y + acc1.y;
    acc.z = acc0.z + acc1.z;
    acc.w = acc0.w + acc1.w;

    if (qt != 0) *(float4*)&shp[rq][qt - 1][lane * 4] = acc;
    __syncthreads();
    if (qt == 0) {
        float4 o1 = *(const float4*)&shp[rq][0][lane * 4];
        float4 o2 = *(const float4*)&shp[rq][1][lane * 4];
        float4 o3 = *(const float4*)&shp[rq][2][lane * 4];
        acc.x = (acc.x + o1.x) + (o2.x + o3.x);
        acc.y = (acc.y + o1.y) + (o2.y + o3.y);
        acc.z = (acc.z + o1.z) + (o2.z + o3.z);
        acc.w = (acc.w + o1.w) + (o2.w + o3.w);

        float hp[4] = {fmaxf(acc.x, 0.f), fmaxf(acc.y, 0.f), fmaxf(acc.z, 0.f), fmaxf(acc.w, 0.f)};
        float4 xv4 = *(const float4*)&g_x[row * 128 + lane * 4];
        float xv[4] = {xv4.x, xv4.y, xv4.z, xv4.w};
        float4 wx4 = *(const float4*)&Wg[lane * 4];
        float4 wh4 = *(const float4*)&Wg[128 + lane * 4];
        float p = xv[0] * wx4.x + xv[1] * wx4.y + xv[2] * wx4.z + xv[3] * wx4.w
                + hp[0] * wh4.x + hp[1] * wh4.y + hp[2] * wh4.z + hp[3] * wh4.w;
#pragma unroll
        for (int o2s = 16; o2s; o2s >>= 1) p += __shfl_xor_sync(0xffffffffu, p, o2s);
        float cf = 1.f / (1.f + expf(-(p + bg[0])));
        float4 ov;
        ov.x = cf * xv[0] + (1.f - cf) * hp[0];
        ov.y = cf * xv[1] + (1.f - cf) * hp[1];
        ov.z = cf * xv[2] + (1.f - cf) * hp[2];
        ov.w = cf * xv[3] + (1.f - cf) * hp[3];
        *(float4*)&g_x[row * 128 + lane * 4] = ov;
    }
}

// ---------------- transpose x: g_xT[k][row] = g_x[row][k] ----------------
__global__ void xpose()
{
    __shared__ float tl[32][33];
    cudaGridDependencySynchronize();
    int r0 = blockIdx.x * 32, c0 = blockIdx.y * 32;
    int lx = threadIdx.x & 31, ly = threadIdx.x >> 5;
#pragma unroll
    for (int rr = ly; rr < 32; rr += 8)
        tl[rr][lx] = g_x[(r0 + rr) * 128 + c0 + lx];
    __syncthreads();
#pragma unroll
    for (int cc = ly; cc < 32; cc += 8)
        g_xT[(c0 + cc) * RTOT + r0 + lx] = tl[lx][cc];
}

// ---------------- u GEMMs: 64x128 tiles, double-buffered cp.async, A transposed ----------------
__global__ void u_gemms(const float* __restrict__ WA1, const float* __restrict__ bA1,
                        const float* __restrict__ WB1, const float* __restrict__ bB1)
{
    __shared__ __align__(16) float As[2][32 * 68];
    __shared__ __align__(16) float Bs[2][32 * 128];
    cudaGridDependencySynchronize();
    int tile = blockIdx.x;
    int arow0;
    const float* B; const float* bias = nullptr; float* C;
    if (tile < 112) {
        int z = tile >> 3, rt = tile & 7;
        arow0 = rt * 64;
        B = (z < 7) ? (WA1 + z * 256 * 128) : (WB1 + (z - 7) * 256 * 128);
        bias = (z < 7) ? (bA1 + z * 128) : (bB1 + (z - 7) * 128);
        C = g_u1 + z * R1T * 128 + rt * 64 * 128;
    } else {
        int t2 = tile - 112; int z = t2 >> 6, rt = t2 & 63;
        arow0 = R1T + rt * 64;
        B = ((z < 7) ? (WA1 + z * 256 * 128) : (WB1 + (z - 7) * 256 * 128)) + 128 * 128;
        C = g_u2 + z * R2T * 128 + rt * 64 * 128;
    }
    int t = threadIdx.x, w = t >> 5, lane = t & 31;
    unsigned long long acc2[4][4];
#pragma unroll
    for (int p = 0; p < 4; p++)
#pragma unroll
        for (int j = 0; j < 4; j++) acc2[p][j] = 0ull;

    auto stage = [&](int buf, int ks) {
        int k0 = ks * 32;
#pragma unroll
        for (int s2 = 0; s2 < 2; s2++) {
            int id = t + 256 * s2;
            int kk = id >> 4, rc = (id & 15) * 4;
            cpa16(&As[buf][kk * 68 + rc], g_xT + (k0 + kk) * RTOT + arow0 + rc);
        }
#pragma unroll
        for (int s2 = 0; s2 < 4; s2++) {
            int id = t + 256 * s2;
            int kk = id >> 5, c = (id & 31) * 4;
            cpa16(&Bs[buf][kk * 128 + c], B + (k0 + kk) * 128 + c);
        }
    };

    stage(0, 0);
    CP_COMMIT();
#pragma unroll
    for (int s = 0; s < 4; s++) {
        if (s + 1 < 4) { stage((s + 1) & 1, s + 1); CP_COMMIT(); }
        if (s + 1 < 4) { CP_WAIT(1); } else { CP_WAIT(0); }
        __syncthreads();
        const float* Ab = As[s & 1];
        const float* Bb = Bs[s & 1];
#pragma unroll
        for (int kk = 0; kk < 32; kk++) {
            const ulonglong2* ap = (const ulonglong2*)&Ab[kk * 68 + w * 8];
            ulonglong2 a0 = ap[0], a1 = ap[1];
            unsigned long long ar[4] = {a0.x, a0.y, a1.x, a1.y};
            float4 bv = *(const float4*)&Bb[kk * 128 + lane * 4];
            unsigned long long br[4] = {dup_f32(bv.x), dup_f32(bv.y), dup_f32(bv.z), dup_f32(bv.w)};
#pragma unroll
            for (int p = 0; p < 4; p++)
#pragma unroll
                for (int j = 0; j < 4; j++) ffma2(acc2[p][j], ar[p], br[j]);
        }
        __syncthreads();
    }
    float4 bvv = make_float4(0.f, 0.f, 0.f, 0.f);
    if (bias) bvv = *(const float4*)&bias[lane * 4];
#pragma unroll
    for (int p = 0; p < 4; p++) {
        float2 v0 = unpk(acc2[p][0]), v1 = unpk(acc2[p][1]);
        float2 v2 = unpk(acc2[p][2]), v3 = unpk(acc2[p][3]);
        float4 olo, ohi;
        olo.x = v0.x + bvv.x; olo.y = v1.x + bvv.y; olo.z = v2.x + bvv.z; olo.w = v3.x + bvv.w;
        ohi.x = v0.y + bvv.x; ohi.y = v1.y + bvv.y; ohi.z = v2.y + bvv.z; ohi.w = v3.y + bvv.w;
        *(float4*)&C[(w * 8 + 2 * p) * 128 + lane * 4] = olo;
        *(float4*)&C[(w * 8 + 2 * p + 1) * 128 + lane * 4] = ohi;
    }
}

// ---------------- pairwise energies (k-major, 16 pairs/warp, vector mask load) ----------------
__global__ void pair_energy(const float* __restrict__ WA2, const float* __restrict__ bA2,
                            const float* __restrict__ WB2, const float* __restrict__ bB2,
                            const float* __restrict__ Cc)
{
    __shared__ __align__(16) float sW[14][128];
    __shared__ float sb2[14], sC[7], sBI[7];
    __shared__ float part[8][7];
    int t = threadIdx.x;
    // weight staging reads only kernel inputs -> overlaps with u_gemms under PDL
    for (int i = t; i < 896; i += 256) sW[i >> 7][i & 127] = WA2[i];
    for (int i = t; i < 896; i += 256) sW[7 + (i >> 7)][i & 127] = WB2[i];
    if (t < 7) {
        sb2[t] = bA2[t]; sC[t] = Cc[t];
        float bb = BCON[t];
        sBI[t] = 1.f / (3.f * bb * bb);
    } else if (t < 14) sb2[t] = bB2[t - 7];
    if (t < 56) part[t / 7][t % 7] = 0.f;
    __syncthreads();
    cudaGridDependencySynchronize();

    int w = t >> 5, lane = t & 31;
    int b = blockIdx.y;
    int pbase = blockIdx.x * 128 + w * 16;        // p = k*64 + j

    uint4 mv;
    if (lane == 0) mv = *(const uint4*)&g_maskb[b * 32768 + pbase];
    mv.x = __shfl_sync(0xffffffffu, mv.x, 0);
    mv.y = __shfl_sync(0xffffffffu, mv.y, 0);
    mv.z = __shfl_sync(0xffffffffu, mv.z, 0);
    mv.w = __shfl_sync(0xffffffffu, mv.w, 0);
    unsigned mw[4] = {mv.x, mv.y, mv.z, mv.w};
    if ((mw[0] | mw[1] | mw[2] | mw[3]) != 0u) {
        for (int q = 0; q < 16; q++) {
            unsigned mask = (mw[q >> 2] >> ((q & 3) * 8)) & 0x7Fu;
            if (!mask) continue;
            int p = pbase + q;
            int j = p & 63, k = p >> 6;
            float dm = g_dm[b * 32768 + p];
            while (mask) {
                int i = __ffs(mask) - 1;
                mask &= mask - 1;
                float4 a1 = ((const float4*)(g_u1 + ((i * BB + b) * NN1 + j) * DD))[lane];
                float4 a2 = ((const float4*)(g_u2 + ((i * BB + b) * NN2 + k) * DD))[lane];
                float4 b1 = ((const float4*)(g_u1 + (((i + 7) * BB + b) * NN1 + j) * DD))[lane];
                float4 b2 = ((const float4*)(g_u2 + (((i + 7) * BB + b) * NN2 + k) * DD))[lane];
                float4 wa = *(const float4*)&sW[i][lane * 4];
                float4 wb = *(const float4*)&sW[7 + i][lane * 4];
                float sa = fmaxf(a1.x + a2.x, 0.f) * wa.x + fmaxf(a1.y + a2.y, 0.f) * wa.y
                         + fmaxf(a1.z + a2.z, 0.f) * wa.z + fmaxf(a1.w + a2.w, 0.f) * wa.w;
                float sb = fmaxf(b1.x + b2.x, 0.f) * wb.x + fmaxf(b1.y + b2.y, 0.f) * wb.y
                         + fmaxf(b1.z + b2.z, 0.f) * wb.z + fmaxf(b1.w + b2.w, 0.f) * wb.w;
#pragma unroll
                for (int o = 16; o; o >>= 1) {
                    sa += __shfl_xor_sync(0xffffffffu, sa, o);
                    sb += __shfl_xor_sync(0xffffffffu, sb, o);
                }
                if (lane == 0) {
                    float Aa = 4.f / (1.f + expf(-(sa + sb2[i])));
                    float bi = sBI[i];
                    float Bp2 = (2.f * bi) / (1.f + expf(-(sb + sb2[7 + i]))) + bi;
                    float dd = dm - sC[i];
                    part[w][i] += Aa * (Bp2 * dd * dd - 1.f);
                }
            }
        }
    }
    __syncthreads();
    if (t < 7) {
        float s = 0.f;
#pragma unroll
        for (int q = 0; q < 8; q++) s += part[q][t];
        g_partial[(b * NBLKP + blockIdx.x) * 7 + t] = s;
    }
}

// ---------------- energy reduce + intercept + output ----------------
__global__ void final_k(const float* __restrict__ valid,
                        const float* __restrict__ Wi1, const float* __restrict__ bi1,
                        const float* __restrict__ Wi2, const float* __restrict__ bi2,
                        float* __restrict__ out)
{
    cudaGridDependencySynchronize();
    int b = blockIdx.x, t = threadIdx.x;
    __shared__ float red[128], energy[7], pooled[128], sv;
    for (int i = 0; i < 7; i++) {
        red[t] = g_partial[(b * NBLKP + t) * 7 + i]
               + g_partial[(b * NBLKP + t + 128) * 7 + i];
        __syncthreads();
        for (int o = 64; o; o >>= 1) {
            if (t < o) red[t] += red[t + o];
            __syncthreads();
        }
        if (t == 0) energy[i] = red[0];
        __syncthreads();
    }
    float s = 0.f;
    for (int j = 0; j < NN1; j++)
        s += g_x[(b * NN1 + j) * DD + t] * valid[b * NN1 + j];
    pooled[t] = s;
    __syncthreads();
    float a = bi1[t];
    for (int d = 0; d < 128; d++) a += pooled[d] * Wi1[d * 128 + t];
    red[t] = fmaxf(a, 0.f) * Wi2[t];
    __syncthreads();
    for (int o = 64; o; o >>= 1) {
        if (t < o) red[t] += red[t + o];
        __syncthreads();
    }
    if (t == 0) sv = 4.f / (1.f + expf(-(red[0] + bi2[0])));
    __syncthreads();
    if (t < 7) out[b * 7 + t] = energy[t] + sv / 7.f;
}

// ---------------- host ----------------
static inline float* symaddr(const void* sym)
{
    void* p = nullptr;
    cudaGetSymbolAddress(&p, sym);
    return (float*)p;
}

template <typename F, typename... Args>
static inline void launch_pdl(F kernel, dim3 grid, dim3 block, Args... args)
{
    cudaLaunchConfig_t cfg = {};
    cfg.gridDim = grid;
    cfg.blockDim = block;
    cfg.dynamicSmemBytes = 0;
    cfg.stream = 0;
    cudaLaunchAttribute at[1];
    at[0].id = cudaLaunchAttributeProgrammaticStreamSerialization;
    at[0].val.programmaticStreamSerializationAllowed = 1;
    cfg.attrs = at;
    cfg.numAttrs = 1;
    cudaLaunchKernelEx(&cfg, kernel, args...);
}

extern "C" void kernel_launch(void* const* d_in, const int* in_sizes, int n_in,
                              void* d_out, int out_size)
{
    (void)in_sizes; (void)n_in; (void)out_size;
    const float* h1      = (const float*)d_in[0];
    const float* adj1    = (const float*)d_in[1];
    const float* h2      = (const float*)d_in[2];
    const float* adj2    = (const float*)d_in[3];
    const float* A_int   = (const float*)d_in[4];
    const float* dmv     = (const float*)d_in[5];
    const float* valid   = (const float*)d_in[6];
    const float* W_embed = (const float*)d_in[7];
    const float* gW      = (const float*)d_in[8];
    const float* gWb     = (const float*)d_in[9];
    const float* gA      = (const float*)d_in[10];
    const float* gGateW  = (const float*)d_in[11];
    const float* gGateb  = (const float*)d_in[12];
    const float* WA1     = (const float*)d_in[13];
    const float* bA1     = (const float*)d_in[14];
    const float* WA2     = (const float*)d_in[15];
    const float* bA2     = (const float*)d_in[16];
    const float* WB1     = (const float*)d_in[17];
    const float* bB1     = (const float*)d_in[18];
    const float* WB2     = (const float*)d_in[19];
    const float* bB2     = (const float*)d_in[20];
    const float* Cw      = (const float*)d_in[21];
    const float* Wi1     = (const float*)d_in[22];
    const float* bi1     = (const float*)d_in[23];
    const float* Wi2     = (const float*)d_in[24];
    const float* bi2     = (const float*)d_in[25];
    float* out = (float*)d_out;

    float* p_wc = symaddr(g_wc);
    float* p_bc = symaddr(g_bc);

    prep<<<PB_E, 256>>>(h1, h2, adj1, adj2, A_int, dmv, W_embed, gW, gA, gWb);

    for (int l = 0; l < NL; l++) {
        launch_pdl(gemm_hc, dim3(144), dim3(256),
                   (const float*)(p_wc + l * DD * 256), (const float*)(p_bc + l * 256));
        launch_pdl(stats_e, dim3(RTOT / 2), dim3(256));
        launch_pdl(att_gate, dim3(RTOT / 2), dim3(256),
                   (const float*)(gGateW + l * 256), (const float*)(gGateb + l));
    }

    launch_pdl(xpose, dim3(RTOT / 32, 4), dim3(256));
    launch_pdl(u_gemms, dim3(1008), dim3(256), WA1, bA1, WB1, bB1);
    launch_pdl(pair_energy, dim3(NBLKP, BB), dim3(256), WA2, bA2, WB2, bB2, Cw);
    launch_pdl(final_k, dim3(BB), dim3(128), valid, Wi1, bi1, Wi2, bi2, out);
}

// round 16
// speedup vs baseline: 1.0245x; 1.0245x over previous
#include <cuda_runtime.h>
#include <math.h>

#define BB 8
#define NN1 64
#define NN2 512
#define DD 128
#define NL 3
#define NT 7
#define R1T (BB*NN1)            // 512
#define R2T (BB*NN2)            // 4096
#define RTOT (R1T+R2T)          // 4608
#define CAP 96
#define NBLKP 256

// ---------------- scratch ----------------
__device__ __align__(16) float g_x  [RTOT*DD];
__device__ __align__(16) float g_xT [DD*RTOT];
__device__ __align__(16) float g_hc [RTOT*256];
__device__ __align__(16) float g_e1 [BB*NN1*NN1];
__device__ __align__(16) float g_e2 [BB*NN2*NN2];
__device__ __align__(16) float g_wc [NL*DD*256];
__device__ __align__(16) float g_bc [NL*256];
__device__ __align__(16) float g_u1 [14*R1T*DD];
__device__ __align__(16) float g_u2 [14*R2T*DD];
__device__ __align__(16) unsigned char g_maskb[BB*NN1*NN2];
__device__ float g_dm[BB*NN1*NN2];
__device__ float g_partial[BB*NBLKP*NT];
__device__ int   g_rl[RTOT*CAP];
__device__ int   g_rcnt[RTOT];
__device__ int   g_cl[RTOT*CAP];
__device__ int   g_ccnt[RTOT];

__constant__ float BCON[7] = {1.159f,0.448f,0.927f,0.902f,0.349f,0.789f,0.198f};

// ---------------- f32x2 / cp.async helpers ----------------
__device__ __forceinline__ unsigned long long dup_f32(float x)
{
    unsigned long long d;
    asm("mov.b64 %0, {%1, %1};" : "=l"(d) : "f"(x));
    return d;
}
__device__ __forceinline__ void ffma2(unsigned long long& acc, unsigned long long a, unsigned long long b)
{
    asm("fma.rn.f32x2 %0, %1, %2, %0;" : "+l"(acc) : "l"(a), "l"(b));
}
__device__ __forceinline__ float2 unpk(unsigned long long v)
{
    float lo, hi;
    asm("mov.b64 {%0, %1}, %2;" : "=f"(lo), "=f"(hi) : "l"(v));
    return make_float2(lo, hi);
}
__device__ __forceinline__ void cpa16(void* smem, const void* g)
{
    unsigned a = (unsigned)__cvta_generic_to_shared(smem);
    asm volatile("cp.async.cg.shared.global [%0], [%1], 16;" :: "r"(a), "l"(g));
}
#define CP_COMMIT() asm volatile("cp.async.commit_group;" ::: "memory")
#define CP_WAIT(n)  asm volatile("cp.async.wait_group %0;" :: "n"(n) : "memory")

// ---------------- 32x128 tile GEMM (scalar, K guarded) ----------------
__device__ __forceinline__ void gemm32_tile(
    const float* __restrict__ A, int lda, int K,
    const float* __restrict__ B, int ldb,
    float* __restrict__ C, int ldc,
    float* As /*32*36*/, float* Bs /*32*128*/)
{
    int t = threadIdx.x, rq = t >> 5, cq = t & 31;
    float acc[4][4];
#pragma unroll
    for (int i = 0; i < 4; i++)
#pragma unroll
        for (int j = 0; j < 4; j++) acc[i][j] = 0.f;
    for (int k0 = 0; k0 < K; k0 += 32) {
#pragma unroll
        for (int s = 0; s < 4; s++) {
            int i = t + 256 * s, r = i >> 5, kk = i & 31, gk = k0 + kk;
            As[kk * 36 + r] = (gk < K) ? A[r * lda + gk] : 0.f;
        }
#pragma unroll
        for (int s = 0; s < 16; s++) {
            int i = t + 256 * s, kk = i >> 7, c = i & 127, gk = k0 + kk;
            Bs[kk * 128 + c] = (gk < K) ? B[gk * ldb + c] : 0.f;
        }
        __syncthreads();
#pragma unroll
        for (int kk = 0; kk < 32; kk++) {
            float4 av = *(const float4*)&As[kk * 36 + rq * 4];
            float4 bv = *(const float4*)&Bs[kk * 128 + cq * 4];
            float ar[4] = {av.x, av.y, av.z, av.w};
            float br[4] = {bv.x, bv.y, bv.z, bv.w};
#pragma unroll
            for (int i = 0; i < 4; i++)
#pragma unroll
                for (int j = 0; j < 4; j++) acc[i][j] += ar[i] * br[j];
        }
        __syncthreads();
    }
#pragma unroll
    for (int i = 0; i < 4; i++) {
        float4 o;
        o.x = acc[i][0]; o.y = acc[i][1]; o.z = acc[i][2]; o.w = acc[i][3];
        *(float4*)&C[(rq * 4 + i) * ldc + cq * 4] = o;
    }
}

// ---------------- 64x128 tile GEMM, K=128, FFMA2 inner (sync staging) ----------------
__device__ __forceinline__ void gemm64_tile(
    const float* __restrict__ A, int lda,
    const float* __restrict__ B, int ldb,
    const float* __restrict__ bias,
    float* __restrict__ C, int ldc,
    float* As /*32*68*/, float* Bs /*32*128*/)
{
    int t = threadIdx.x, w = t >> 5, lane = t & 31;
    unsigned long long acc2[4][4];
#pragma unroll
    for (int p = 0; p < 4; p++)
#pragma unroll
        for (int j = 0; j < 4; j++) acc2[p][j] = 0ull;
    for (int k0 = 0; k0 < 128; k0 += 32) {
#pragma unroll
        for (int s = 0; s < 8; s++) {
            int i = t + 256 * s, r = i >> 5, kk = i & 31;
            As[kk * 68 + r] = A[r * lda + k0 + kk];
        }
#pragma unroll
        for (int s = 0; s < 16; s++) {
            int i = t + 256 * s, kk = i >> 7, c = i & 127;
            Bs[kk * 128 + c] = B[(k0 + kk) * ldb + c];
        }
        __syncthreads();
#pragma unroll
        for (int kk = 0; kk < 32; kk++) {
            const ulonglong2* ap = (const ulonglong2*)&As[kk * 68 + w * 8];
            ulonglong2 a0 = ap[0], a1 = ap[1];
            unsigned long long ar[4] = {a0.x, a0.y, a1.x, a1.y};
            float4 bv = *(const float4*)&Bs[kk * 128 + lane * 4];
            unsigned long long br[4] = {dup_f32(bv.x), dup_f32(bv.y), dup_f32(bv.z), dup_f32(bv.w)};
#pragma unroll
            for (int p = 0; p < 4; p++)
#pragma unroll
                for (int j = 0; j < 4; j++) ffma2(acc2[p][j], ar[p], br[j]);
        }
        __syncthreads();
    }
    float4 bvv = make_float4(0.f, 0.f, 0.f, 0.f);
    if (bias) bvv = *(const float4*)&bias[lane * 4];
#pragma unroll
    for (int p = 0; p < 4; p++) {
        float2 v0 = unpk(acc2[p][0]), v1 = unpk(acc2[p][1]);
        float2 v2 = unpk(acc2[p][2]), v3 = unpk(acc2[p][3]);
        float4 olo, ohi;
        olo.x = v0.x + bvv.x; olo.y = v1.x + bvv.y; olo.z = v2.x + bvv.z; olo.w = v3.x + bvv.w;
        ohi.x = v0.y + bvv.x; ohi.y = v1.y + bvv.y; ohi.z = v2.y + bvv.z; ohi.w = v3.y + bvv.w;
        *(float4*)&C[(w * 8 + 2 * p) * ldc + lane * 4] = olo;
        *(float4*)&C[(w * 8 + 2 * p + 1) * ldc + lane * 4] = ohi;
    }
}

// ---------------- prep: weights || col-lists || row-lists || mask+dm || embed ----------------
#define PB_A 192
#define PB_B (PB_A + 18)
#define PB_C (PB_B + 576)
#define PB_D (PB_C + 1024)
#define PB_E (PB_D + 144)

__global__ void prep(const float* __restrict__ h1, const float* __restrict__ h2,
                     const float* __restrict__ adj1, const float* __restrict__ adj2,
                     const float* __restrict__ A_int, const float* __restrict__ dmv,
                     const float* __restrict__ W_embed,
                     const float* __restrict__ gW, const float* __restrict__ gA,
                     const float* __restrict__ gWb)
{
    __shared__ __align__(16) float shA[32 * 36];
    __shared__ __align__(16) float shB[32 * 128];
    int bx = blockIdx.x, t = threadIdx.x;

    if (bx < PB_A) {
        int idx = bx * 256 + t;
        int c = idx & 127, d = (idx >> 7) & 127, l = idx >> 14;
        const float* W = gW + l * DD * DD;
        const float* Am = gA + l * DD * DD;
        g_wc[(l * DD + d) * 256 + c] = W[d * DD + c];
        float s = 0.f;
#pragma unroll 8
        for (int dd = 0; dd < DD; dd++) s += W[d * DD + dd] * Am[dd * DD + c];
        g_wc[(l * DD + d) * 256 + 128 + c] = s;
        if (d == 0) {
            g_bc[l * 256 + c] = gWb[l * DD + c];
            float sb = 0.f;
#pragma unroll 8
            for (int dd = 0; dd < DD; dd++) sb += gWb[l * DD + dd] * Am[dd * DD + c];
            g_bc[l * 256 + 128 + c] = sb;
        }
    } else if (bx < PB_B) {
        int cidx = (bx - PB_A) * 256 + t;
        const float* aj; int N, c;
        if (cidx < R1T) { int b = cidx >> 6; c = cidx & 63; N = NN1; aj = adj1 + b * NN1 * NN1; }
        else { int rr = cidx - R1T; int b = rr >> 9; c = rr & 511; N = NN2; aj = adj2 + b * NN2 * NN2; }
        int cnt = 0;
        for (int r = 0; r < N; r++) {
            if (aj[r * N + c] != 0.f) { if (cnt < CAP) g_cl[cidx * CAP + cnt] = r; cnt++; }
        }
        g_ccnt[cidx] = (cnt > CAP) ? CAP : cnt;
    } else if (bx < PB_C) {
        int row = (bx - PB_B) * 8 + (t >> 5);
        int lane = t & 31;
        const float* aj; int N;
        if (row < R1T) { int b = row >> 6, r = row & 63; N = NN1; aj = adj1 + (b * NN1 + r) * NN1; }
        else { int rr = row - R1T; int b = rr >> 9, r = rr & 511; N = NN2; aj = adj2 + (b * NN2 + r) * NN2; }
        int cnt = 0;
        for (int base = 0; base < N; base += 32) {
            int c = base + lane;
            bool v = (aj[c] != 0.f);
            unsigned m = __ballot_sync(0xffffffffu, v);
            if (v) {
                int pos = cnt + __popc(m & ((1u << lane) - 1u));
                if (pos < CAP) g_rl[row * CAP + pos] = c;
            }
            cnt += __popc(m);
        }
        if (cnt > CAP) cnt = CAP;
        if (lane == 0) g_rcnt[row] = cnt;
    } else if (bx < PB_D) {
        int v = (bx - PB_C) * 256 + t;
        int k = v & 511, j = (v >> 9) & 63, b = v >> 15;
        unsigned m = 0;
#pragma unroll
        for (int i = 0; i < 7; i++)
            if (A_int[((b * 7 + i) * NN1 + j) * NN2 + k] != 0.f) m |= 1u << i;
        int po = b * 32768 + k * 64 + j;
        g_maskb[po] = (unsigned char)m;
        int pidx = (b * NN1 + j) * NN2 + k;
        float d0 = dmv[pidx * 3 + 0], d1 = dmv[pidx * 3 + 1], d2 = dmv[pidx * 3 + 2];
        float dm = sqrtf(d0 * d0 + d1 * d1 + d2 * d2 + 1e-10f);
        if (dm < 0.5f) dm = 1e10f;
        g_dm[po] = dm;
    } else {
        int tile = bx - PB_D;
        int row0 = tile * 32;
        const float* Ap = (row0 < R1T) ? (h1 + row0 * 56) : (h2 + (row0 - R1T) * 56);
        gemm32_tile(Ap, 56, 56, W_embed, 128, g_x + row0 * 128, 128, shA, shB);
    }
}

// ---------------- layer GEMM: hc = x @ Wc + bc ----------------
__global__ void gemm_hc(const float* __restrict__ wc_l, const float* __restrict__ bc_l)
{
    __shared__ __align__(16) float shA[32 * 68];
    __shared__ __align__(16) float shB[32 * 128];
    cudaGridDependencySynchronize();
    int rowtile = blockIdx.x >> 1, colb = blockIdx.x & 1;
    gemm64_tile(g_x + rowtile * 64 * 128, 128,
                wc_l + colb * 128, 256,
                bc_l + colb * 128,
                g_hc + rowtile * 64 * 256 + colb * 128, 256, shA, shB);
}

// ---------------- column pass: e -> normalized att (4 warps/column, 1 col/block, 128 thr) ----------------
__global__ void stats_e()
{
    __shared__ float smx[4];
    __shared__ float ssum[4];
    cudaGridDependencySynchronize();
    int qt = threadIdx.x >> 5, lane = threadIdx.x & 31;
    int cidx = blockIdx.x;
    int N, c, gbase; float* E;
    if (cidx < R1T) { int b = cidx >> 6; c = cidx & 63; N = NN1; gbase = b * NN1; E = g_e1 + b * NN1 * NN1; }
    else { int rr = cidx - R1T; int b = rr >> 9; c = rr & 511; N = NN2; gbase = R1T + b * NN2; E = g_e2 + b * NN2 * NN2; }

    float4 hcv  = *(const float4*)&g_hc[(gbase + c) * 256 + lane * 4];
    float4 hacv = *(const float4*)&g_hc[(gbase + c) * 256 + 128 + lane * 4];
    int cnt = g_ccnt[cidx];
    const int* cl = g_cl + cidx * CAP;
    int qlen = (cnt + 3) >> 2;
    int s0 = qt * qlen;
    int s1 = s0 + qlen; if (s1 > cnt) s1 = cnt;
    int len = s1 - s0; if (len < 0) len = 0;      // <= 24

    float ebuf = 0.f;
    float mx = -1e30f;
    int idx = 0;
    for (; idx + 4 <= len; idx += 4) {
        float e[4];
#pragma unroll
        for (int u = 0; u < 4; u++) {
            int r = cl[s0 + idx + u];
            const float* pr = &g_hc[(gbase + r) * 256 + lane * 4];
            float4 h = *(const float4*)pr;
            float4 ha = *(const float4*)(pr + 128);
            e[u] = hacv.x * h.x + hacv.y * h.y + hacv.z * h.z + hacv.w * h.w
                 + hcv.x * ha.x + hcv.y * ha.y + hcv.z * ha.z + hcv.w * ha.w;
        }
#pragma unroll
        for (int o = 16; o; o >>= 1) {
#pragma unroll
            for (int u = 0; u < 4; u++)
                e[u] += __shfl_xor_sync(0xffffffffu, e[u], o);
        }
#pragma unroll
        for (int u = 0; u < 4; u++) {
            if (lane == (idx + u)) ebuf = e[u];
            mx = fmaxf(mx, e[u]);
        }
    }
    for (; idx < len; idx++) {
        int r = cl[s0 + idx];
        const float* pr = &g_hc[(gbase + r) * 256 + lane * 4];
        float4 hr = *(const float4*)pr, har = *(const float4*)(pr + 128);
        float p = hacv.x * hr.x + hacv.y * hr.y + hacv.z * hr.z + hacv.w * hr.w
                + hcv.x * har.x + hcv.y * har.y + hcv.z * har.z + hcv.w * har.w;
#pragma unroll
        for (int o = 16; o; o >>= 1) p += __shfl_xor_sync(0xffffffffu, p, o);
        if (lane == idx) ebuf = p;
        mx = fmaxf(mx, p);
    }
    if (lane == 0) smx[qt] = mx;
    __syncthreads();
    float gmx = fmaxf(fmaxf(smx[0], smx[1]), fmaxf(smx[2], smx[3]));

    float vb = 0.f;
    float s = 0.f;
    if (lane < len) { vb = expf(ebuf - gmx); s = vb; }
#pragma unroll
    for (int o = 16; o; o >>= 1) s += __shfl_xor_sync(0xffffffffu, s, o);
    if (lane == 0) ssum[qt] = s;
    __syncthreads();
    float zi = 1.f / ((ssum[0] + ssum[1]) + (ssum[2] + ssum[3]));
    if (lane < len) E[cl[s0 + lane] * N + c] = vb * zi;
}

// ---------------- row pass: hp = relu(att@h); gate (4 warps/row, 1 row/block, 128 thr) ----------------
__global__ void att_gate(const float* __restrict__ Wg, const float* __restrict__ bg)
{
    __shared__ __align__(16) float shp[3][128];
    cudaGridDependencySynchronize();
    int qt = threadIdx.x >> 5, lane = threadIdx.x & 31;
    int row = blockIdx.x;
    int N, r, gbase; const float* E;
    if (row < R1T) { int b = row >> 6; r = row & 63; N = NN1; gbase = b * NN1; E = g_e1 + b * NN1 * NN1; }
    else { int rr = row - R1T; int b = rr >> 9; r = rr & 511; N = NN2; gbase = R1T + b * NN2; E = g_e2 + b * NN2 * NN2; }

    float4 acc0 = make_float4(0.f, 0.f, 0.f, 0.f);
    float4 acc1 = make_float4(0.f, 0.f, 0.f, 0.f);
    int cnt = g_rcnt[row];
    const int* rl = g_rl + row * CAP;
    const float* Er = E + r * N;
    int qlen = (cnt + 3) >> 2;
    int s0 = qt * qlen;
    int s1 = s0 + qlen; if (s1 > cnt) s1 = cnt;
    int idx = s0;
    for (; idx + 4 <= s1; idx += 4) {
        int c0 = rl[idx], c1 = rl[idx + 1], c2 = rl[idx + 2], c3 = rl[idx + 3];
        float w0 = Er[c0], w1 = Er[c1], w2 = Er[c2], w3 = Er[c3];
        float4 h0 = *(const float4*)&g_hc[(gbase + c0) * 256 + lane * 4];
        float4 h1 = *(const float4*)&g_hc[(gbase + c1) * 256 + lane * 4];
        float4 h2 = *(const float4*)&g_hc[(gbase + c2) * 256 + lane * 4];
        float4 h3 = *(const float4*)&g_hc[(gbase + c3) * 256 + lane * 4];
        acc0.x += w0 * h0.x; acc0.y += w0 * h0.y; acc0.z += w0 * h0.z; acc0.w += w0 * h0.w;
        acc1.x += w1 * h1.x; acc1.y += w1 * h1.y; acc1.z += w1 * h1.z; acc1.w += w1 * h1.w;
        acc0.x += w2 * h2.x; acc0.y += w2 * h2.y; acc0.z += w2 * h2.z; acc0.w += w2 * h2.w;
        acc1.x += w3 * h3.x; acc1.y += w3 * h3.y; acc1.z += w3 * h3.z; acc1.w += w3 * h3.w;
    }
    for (; idx < s1; idx++) {
        int cc = rl[idx];
        float wv = Er[cc];
        float4 hv = *(const float4*)&g_hc[(gbase + cc) * 256 + lane * 4];
        acc0.x += wv * hv.x; acc0.y += wv * hv.y; acc0.z += wv * hv.z; acc0.w += wv * hv.w;
    }
    float4 acc;
    acc.x = acc0.x + acc1.x;
    acc.y = acc0.y + acc1.y;
    acc.z = acc0.z + acc1.z;
    acc.w = acc0.w + acc1.w;

    if (qt != 0) *(float4*)&shp[qt - 1][lane * 4] = acc;
    __syncthreads();
    if (qt == 0) {
        float4 o1 = *(const float4*)&shp[0][lane * 4];
        float4 o2 = *(const float4*)&shp[1][lane * 4];
        float4 o3 = *(const float4*)&shp[2][lane * 4];
        acc.x = (acc.x + o1.x) + (o2.x + o3.x);
        acc.y = (acc.y + o1.y) + (o2.y + o3.y);
        acc.z = (acc.z + o1.z) + (o2.z + o3.z);
        acc.w = (acc.w + o1.w) + (o2.w + o3.w);

        float hp[4] = {fmaxf(acc.x, 0.f), fmaxf(acc.y, 0.f), fmaxf(acc.z, 0.f), fmaxf(acc.w, 0.f)};
        float4 xv4 = *(const float4*)&g_x[row * 128 + lane * 4];
        float xv[4] = {xv4.x, xv4.y, xv4.z, xv4.w};
        float4 wx4 = *(const float4*)&Wg[lane * 4];
        float4 wh4 = *(const float4*)&Wg[128 + lane * 4];
        float p = xv[0] * wx4.x + xv[1] * wx4.y + xv[2] * wx4.z + xv[3] * wx4.w
                + hp[0] * wh4.x + hp[1] * wh4.y + hp[2] * wh4.z + hp[3] * wh4.w;
#pragma unroll
        for (int o2s = 16; o2s; o2s >>= 1) p += __shfl_xor_sync(0xffffffffu, p, o2s);
        float cf = 1.f / (1.f + expf(-(p + bg[0])));
        float4 ov;
        ov.x = cf * xv[0] + (1.f - cf) * hp[0];
        ov.y = cf * xv[1] + (1.f - cf) * hp[1];
        ov.z = cf * xv[2] + (1.f - cf) * hp[2];
        ov.w = cf * xv[3] + (1.f - cf) * hp[3];
        *(float4*)&g_x[row * 128 + lane * 4] = ov;
    }
}

// ---------------- transpose x: g_xT[k][row] = g_x[row][k] ----------------
__global__ void xpose()
{
    __shared__ float tl[32][33];
    cudaGridDependencySynchronize();
    int r0 = blockIdx.x * 32, c0 = blockIdx.y * 32;
    int lx = threadIdx.x & 31, ly = threadIdx.x >> 5;
#pragma unroll
    for (int rr = ly; rr < 32; rr += 8)
        tl[rr][lx] = g_x[(r0 + rr) * 128 + c0 + lx];
    __syncthreads();
#pragma unroll
    for (int cc = ly; cc < 32; cc += 8)
        g_xT[(c0 + cc) * RTOT + r0 + lx] = tl[lx][cc];
}

// ---------------- u GEMMs: 64x128 tiles, double-buffered cp.async, A transposed ----------------
__global__ void u_gemms(const float* __restrict__ WA1, const float* __restrict__ bA1,
                        const float* __restrict__ WB1, const float* __restrict__ bB1)
{
    __shared__ __align__(16) float As[2][32 * 68];
    __shared__ __align__(16) float Bs[2][32 * 128];
    cudaGridDependencySynchronize();
    int tile = blockIdx.x;
    int arow0;
    const float* B; const float* bias = nullptr; float* C;
    if (tile < 112) {
        int z = tile >> 3, rt = tile & 7;
        arow0 = rt * 64;
        B = (z < 7) ? (WA1 + z * 256 * 128) : (WB1 + (z - 7) * 256 * 128);
        bias = (z < 7) ? (bA1 + z * 128) : (bB1 + (z - 7) * 128);
        C = g_u1 + z * R1T * 128 + rt * 64 * 128;
    } else {
        int t2 = tile - 112; int z = t2 >> 6, rt = t2 & 63;
        arow0 = R1T + rt * 64;
        B = ((z < 7) ? (WA1 + z * 256 * 128) : (WB1 + (z - 7) * 256 * 128)) + 128 * 128;
        C = g_u2 + z * R2T * 128 + rt * 64 * 128;
    }
    int t = threadIdx.x, w = t >> 5, lane = t & 31;
    unsigned long long acc2[4][4];
#pragma unroll
    for (int p = 0; p < 4; p++)
#pragma unroll
        for (int j = 0; j < 4; j++) acc2[p][j] = 0ull;

    auto stage = [&](int buf, int ks) {
        int k0 = ks * 32;
#pragma unroll
        for (int s2 = 0; s2 < 2; s2++) {
            int id = t + 256 * s2;
            int kk = id >> 4, rc = (id & 15) * 4;
            cpa16(&As[buf][kk * 68 + rc], g_xT + (k0 + kk) * RTOT + arow0 + rc);
        }
#pragma unroll
        for (int s2 = 0; s2 < 4; s2++) {
            int id = t + 256 * s2;
            int kk = id >> 5, c = (id & 31) * 4;
            cpa16(&Bs[buf][kk * 128 + c], B + (k0 + kk) * 128 + c);
        }
    };

    stage(0, 0);
    CP_COMMIT();
#pragma unroll
    for (int s = 0; s < 4; s++) {
        if (s + 1 < 4) { stage((s + 1) & 1, s + 1); CP_COMMIT(); }
        if (s + 1 < 4) { CP_WAIT(1); } else { CP_WAIT(0); }
        __syncthreads();
        const float* Ab = As[s & 1];
        const float* Bb = Bs[s & 1];
#pragma unroll
        for (int kk = 0; kk < 32; kk++) {
            const ulonglong2* ap = (const ulonglong2*)&Ab[kk * 68 + w * 8];
            ulonglong2 a0 = ap[0], a1 = ap[1];
            unsigned long long ar[4] = {a0.x, a0.y, a1.x, a1.y};
            float4 bv = *(const float4*)&Bb[kk * 128 + lane * 4];
            unsigned long long br[4] = {dup_f32(bv.x), dup_f32(bv.y), dup_f32(bv.z), dup_f32(bv.w)};
#pragma unroll
            for (int p = 0; p < 4; p++)
#pragma unroll
                for (int j = 0; j < 4; j++) ffma2(acc2[p][j], ar[p], br[j]);
        }
        __syncthreads();
    }
    float4 bvv = make_float4(0.f, 0.f, 0.f, 0.f);
    if (bias) bvv = *(const float4*)&bias[lane * 4];
#pragma unroll
    for (int p = 0; p < 4; p++) {
        float2 v0 = unpk(acc2[p][0]), v1 = unpk(acc2[p][1]);
        float2 v2 = unpk(acc2[p][2]), v3 = unpk(acc2[p][3]);
        float4 olo, ohi;
        olo.x = v0.x + bvv.x; olo.y = v1.x + bvv.y; olo.z = v2.x + bvv.z; olo.w = v3.x + bvv.w;
        ohi.x = v0.y + bvv.x; ohi.y = v1.y + bvv.y; ohi.z = v2.y + bvv.z; ohi.w = v3.y + bvv.w;
        *(float4*)&C[(w * 8 + 2 * p) * 128 + lane * 4] = olo;
        *(float4*)&C[(w * 8 + 2 * p + 1) * 128 + lane * 4] = ohi;
    }
}

// ---------------- pairwise energies (k-major, 16 pairs/warp, vector mask load) ----------------
__global__ void pair_energy(const float* __restrict__ WA2, const float* __restrict__ bA2,
                            const float* __restrict__ WB2, const float* __restrict__ bB2,
                            const float* __restrict__ Cc)
{
    __shared__ __align__(16) float sW[14][128];
    __shared__ float sb2[14], sC[7], sBI[7];
    __shared__ float part[8][7];
    int t = threadIdx.x;
    // weight staging reads only kernel inputs -> overlaps with u_gemms under PDL
    for (int i = t; i < 896; i += 256) sW[i >> 7][i & 127] = WA2[i];
    for (int i = t; i < 896; i += 256) sW[7 + (i >> 7)][i & 127] = WB2[i];
    if (t < 7) {
        sb2[t] = bA2[t]; sC[t] = Cc[t];
        float bb = BCON[t];
        sBI[t] = 1.f / (3.f * bb * bb);
    } else if (t < 14) sb2[t] = bB2[t - 7];
    if (t < 56) part[t / 7][t % 7] = 0.f;
    __syncthreads();
    cudaGridDependencySynchronize();

    int w = t >> 5, lane = t & 31;
    int b = blockIdx.y;
    int pbase = blockIdx.x * 128 + w * 16;        // p = k*64 + j

    uint4 mv;
    if (lane == 0) mv = *(const uint4*)&g_maskb[b * 32768 + pbase];
    mv.x = __shfl_sync(0xffffffffu, mv.x, 0);
    mv.y = __shfl_sync(0xffffffffu, mv.y, 0);
    mv.z = __shfl_sync(0xffffffffu, mv.z, 0);
    mv.w = __shfl_sync(0xffffffffu, mv.w, 0);
    unsigned mw[4] = {mv.x, mv.y, mv.z, mv.w};
    if ((mw[0] | mw[1] | mw[2] | mw[3]) != 0u) {
        for (int q = 0; q < 16; q++) {
            unsigned mask = (mw[q >> 2] >> ((q & 3) * 8)) & 0x7Fu;
            if (!mask) continue;
            int p = pbase + q;
            int j = p & 63, k = p >> 6;
            float dm = g_dm[b * 32768 + p];
            while (mask) {
                int i = __ffs(mask) - 1;
                mask &= mask - 1;
                float4 a1 = ((const float4*)(g_u1 + ((i * BB + b) * NN1 + j) * DD))[lane];
                float4 a2 = ((const float4*)(g_u2 + ((i * BB + b) * NN2 + k) * DD))[lane];
                float4 b1 = ((const float4*)(g_u1 + (((i + 7) * BB + b) * NN1 + j) * DD))[lane];
                float4 b2 = ((const float4*)(g_u2 + (((i + 7) * BB + b) * NN2 + k) * DD))[lane];
                float4 wa = *(const float4*)&sW[i][lane * 4];
                float4 wb = *(const float4*)&sW[7 + i][lane * 4];
                float sa = fmaxf(a1.x + a2.x, 0.f) * wa.x + fmaxf(a1.y + a2.y, 0.f) * wa.y
                         + fmaxf(a1.z + a2.z, 0.f) * wa.z + fmaxf(a1.w + a2.w, 0.f) * wa.w;
                float sb = fmaxf(b1.x + b2.x, 0.f) * wb.x + fmaxf(b1.y + b2.y, 0.f) * wb.y
                         + fmaxf(b1.z + b2.z, 0.f) * wb.z + fmaxf(b1.w + b2.w, 0.f) * wb.w;
#pragma unroll
                for (int o = 16; o; o >>= 1) {
                    sa += __shfl_xor_sync(0xffffffffu, sa, o);
                    sb += __shfl_xor_sync(0xffffffffu, sb, o);
                }
                if (lane == 0) {
                    float Aa = 4.f / (1.f + expf(-(sa + sb2[i])));
                    float bi = sBI[i];
                    float Bp2 = (2.f * bi) / (1.f + expf(-(sb + sb2[7 + i]))) + bi;
                    float dd = dm - sC[i];
                    part[w][i] += Aa * (Bp2 * dd * dd - 1.f);
                }
            }
        }
    }
    __syncthreads();
    if (t < 7) {
        float s = 0.f;
#pragma unroll
        for (int q = 0; q < 8; q++) s += part[q][t];
        g_partial[(b * NBLKP + blockIdx.x) * 7 + t] = s;
    }
}

// ---------------- energy reduce + intercept + output ----------------
__global__ void final_k(const float* __restrict__ valid,
                        const float* __restrict__ Wi1, const float* __restrict__ bi1,
                        const float* __restrict__ Wi2, const float* __restrict__ bi2,
                        float* __restrict__ out)
{
    cudaGridDependencySynchronize();
    int b = blockIdx.x, t = threadIdx.x;
    __shared__ float red[128], energy[7], pooled[128], sv;
    for (int i = 0; i < 7; i++) {
        red[t] = g_partial[(b * NBLKP + t) * 7 + i]
               + g_partial[(b * NBLKP + t + 128) * 7 + i];
        __syncthreads();
        for (int o = 64; o; o >>= 1) {
            if (t < o) red[t] += red[t + o];
            __syncthreads();
        }
        if (t == 0) energy[i] = red[0];
        __syncthreads();
    }
    float s = 0.f;
    for (int j = 0; j < NN1; j++)
        s += g_x[(b * NN1 + j) * DD + t] * valid[b * NN1 + j];
    pooled[t] = s;
    __syncthreads();
    float a = bi1[t];
    for (int d = 0; d < 128; d++) a += pooled[d] * Wi1[d * 128 + t];
    red[t] = fmaxf(a, 0.f) * Wi2[t];
    __syncthreads();
    for (int o = 64; o; o >>= 1) {
        if (t < o) red[t] += red[t + o];
        __syncthreads();
    }
    if (t == 0) sv = 4.f / (1.f + expf(-(red[0] + bi2[0])));
    __syncthreads();
    if (t < 7) out[b * 7 + t] = energy[t] + sv / 7.f;
}

// ---------------- host ----------------
static inline float* symaddr(const void* sym)
{
    void* p = nullptr;
    cudaGetSymbolAddress(&p, sym);
    return (float*)p;
}

template <typename F, typename... Args>
static inline void launch_pdl(F kernel, dim3 grid, dim3 block, Args... args)
{
    cudaLaunchConfig_t cfg = {};
    cfg.gridDim = grid;
    cfg.blockDim = block;
    cfg.dynamicSmemBytes = 0;
    cfg.stream = 0;
    cudaLaunchAttribute at[1];
    at[0].id = cudaLaunchAttributeProgrammaticStreamSerialization;
    at[0].val.programmaticStreamSerializationAllowed = 1;
    cfg.attrs = at;
    cfg.numAttrs = 1;
    cudaLaunchKernelEx(&cfg, kernel, args...);
}

extern "C" void kernel_launch(void* const* d_in, const int* in_sizes, int n_in,
                              void* d_out, int out_size)
{
    (void)in_sizes; (void)n_in; (void)out_size;
    const float* h1      = (const float*)d_in[0];
    const float* adj1    = (const float*)d_in[1];
    const float* h2      = (const float*)d_in[2];
    const float* adj2    = (const float*)d_in[3];
    const float* A_int   = (const float*)d_in[4];
    const float* dmv     = (const float*)d_in[5];
    const float* valid   = (const float*)d_in[6];
    const float* W_embed = (const float*)d_in[7];
    const float* gW      = (const float*)d_in[8];
    const float* gWb     = (const float*)d_in[9];
    const float* gA      = (const float*)d_in[10];
    const float* gGateW  = (const float*)d_in[11];
    const float* gGateb  = (const float*)d_in[12];
    const float* WA1     = (const float*)d_in[13];
    const float* bA1     = (const float*)d_in[14];
    const float* WA2     = (const float*)d_in[15];
    const float* bA2     = (const float*)d_in[16];
    const float* WB1     = (const float*)d_in[17];
    const float* bB1     = (const float*)d_in[18];
    const float* WB2     = (const float*)d_in[19];
    const float* bB2     = (const float*)d_in[20];
    const float* Cw      = (const float*)d_in[21];
    const float* Wi1     = (const float*)d_in[22];
    const float* bi1     = (const float*)d_in[23];
    const float* Wi2     = (const float*)d_in[24];
    const float* bi2     = (const float*)d_in[25];
    float* out = (float*)d_out;

    float* p_wc = symaddr(g_wc);
    float* p_bc = symaddr(g_bc);

    prep<<<PB_E, 256>>>(h1, h2, adj1, adj2, A_int, dmv, W_embed, gW, gA, gWb);

    for (int l = 0; l < NL; l++) {
        launch_pdl(gemm_hc, dim3(144), dim3(256),
                   (const float*)(p_wc + l * DD * 256), (const float*)(p_bc + l * 256));
        launch_pdl(stats_e, dim3(RTOT), dim3(128));
        launch_pdl(att_gate, dim3(RTOT), dim3(128),
                   (const float*)(gGateW + l * 256), (const float*)(gGateb + l));
    }

    launch_pdl(xpose, dim3(RTOT / 32, 4), dim3(256));
    launch_pdl(u_gemms, dim3(1008), dim3(256), WA1, bA1, WB1, bB1);
    launch_pdl(pair_energy, dim3(NBLKP, BB), dim3(256), WA2, bA2, WB2, bB2, Cw);
    launch_pdl(final_k, dim3(BB), dim3(128), valid, Wi1, bi1, Wi2, bi2, out);
}